// round 6
// baseline (speedup 1.0000x reference)
#include <cuda_runtime.h>
#include <math.h>
#include <stdint.h>

// ---------------- problem constants ----------------
#define Bx      16
#define Lx      64
#define Nx      1024
#define HAND    99
#define Jx      21
#define HIDD    512
#define NLAYERS 4
#define NHEADS  8
#define DHD     64
#define CATD    2273
#define SEQ     128          // 2*Lx
#define M1      (Bx*Lx)      // 1024 rows per hand
#define M2      (Bx*SEQ)     // 2048 transformer rows

// ---------------- scratch (single __device__ arena) ----------------
#define OFF_PCT   0
#define SZ_PCT    (M1*Nx*3)
#define OFF_PCN   (OFF_PCT + SZ_PCT)
#define SZ_PCN    (M1*Nx)
#define OFF_ATT   (OFF_PCN + SZ_PCN)
#define SZ_ATT    (2*M1*Jx*3)
#define OFF_CAT   (OFF_ATT + SZ_ATT)
#define SZ_CAT    (2*M1*CATD)
#define OFF_FC    (OFF_CAT + SZ_CAT)
#define SZ_FC     (2*M1*HIDD)
#define OFF_X     (OFF_FC + SZ_FC)
#define SZ_X      (M2*HIDD)
#define OFF_H     (OFF_X + SZ_X)
#define SZ_H      (M2*HIDD)
#define OFF_QKV   (OFF_H + SZ_H)
#define SZ_QKV    (M2*3*HIDD)
#define OFF_AO    (OFF_QKV + SZ_QKV)
#define SZ_AO     (M2*HIDD)
#define OFF_FF    (OFF_AO + SZ_AO)
#define SZ_FF     (M2*4*HIDD)
#define OFF_TMP   (OFF_FF + SZ_FF)
#define SZ_TMP    (M2*HIDD)
#define SCRATCH_TOTAL (OFF_TMP + SZ_TMP)

__device__ float g_scratch[SCRATCH_TOTAL];

// ---------------- rot6d + pc transform + norm ----------------
__global__ void transform_kernel(const float* __restrict__ x_obj,
                                 const float* __restrict__ pc,
                                 float* __restrict__ pct,
                                 float* __restrict__ pcn) {
    int bl = blockIdx.x;
    int b  = bl / Lx;
    const float* xo = x_obj + (size_t)bl * 10;
    float tx = xo[0], ty = xo[1], tz = xo[2];
    float a1x = xo[3], a1y = xo[4], a1z = xo[5];
    float a2x = xo[6], a2y = xo[7], a2z = xo[8];
    float n1 = sqrtf(a1x*a1x + a1y*a1y + a1z*a1z);
    float b1x = a1x/n1, b1y = a1y/n1, b1z = a1z/n1;
    float dd  = b1x*a2x + b1y*a2y + b1z*a2z;
    float b2x = a2x - dd*b1x, b2y = a2y - dd*b1y, b2z = a2z - dd*b1z;
    float n2 = sqrtf(b2x*b2x + b2y*b2y + b2z*b2z);
    b2x /= n2; b2y /= n2; b2z /= n2;
    float b3x = b1y*b2z - b1z*b2y;
    float b3y = b1z*b2x - b1x*b2z;
    float b3z = b1x*b2y - b1y*b2x;
    const float* pcb = pc + (size_t)b * Nx * 3;
    for (int n = threadIdx.x; n < Nx; n += blockDim.x) {
        float px = pcb[n*3+0], py = pcb[n*3+1], pz = pcb[n*3+2];
        float ox = b1x*px + b2x*py + b3x*pz + tx;
        float oy = b1y*px + b2y*py + b3y*pz + ty;
        float oz = b1z*px + b2z*py + b3z*pz + tz;
        float* o = pct + ((size_t)bl * Nx + n) * 3;
        o[0] = ox; o[1] = oy; o[2] = oz;
        pcn[(size_t)bl * Nx + n] = sqrtf(ox*ox + oy*oy + oz*oz);
    }
}

// ---------------- nearest-point attention map ----------------
__global__ void attmap_kernel(const float* __restrict__ jl,
                              const float* __restrict__ jr,
                              const float* __restrict__ pct,
                              float* __restrict__ att) {
    __shared__ float pcs[Nx*3];
    int bl = blockIdx.x, hand = blockIdx.y;
    const float* src = pct + (size_t)bl * Nx * 3;
    for (int i = threadIdx.x; i < Nx*3; i += blockDim.x) pcs[i] = src[i];
    __syncthreads();
    int w = threadIdx.x >> 5, lane = threadIdx.x & 31;
    if (w >= Jx) return;
    const float* jp = (hand ? jr : jl) + ((size_t)bl * Jx + w) * 3;
    float jx = jp[0], jy = jp[1], jz = jp[2];
    float jj = jx*jx + jy*jy + jz*jz;
    float best = 3.4e38f; int bidx = Nx;
    for (int n = lane; n < Nx; n += 32) {
        float px = pcs[n*3+0], py = pcs[n*3+1], pz = pcs[n*3+2];
        float pp = px*px + py*py + pz*pz;
        float d2 = jj + pp - 2.f*(jx*px + jy*py + jz*pz);
        if (d2 < best || (d2 == best && n < bidx)) { best = d2; bidx = n; }
    }
    for (int o = 16; o; o >>= 1) {
        float ob = __shfl_down_sync(0xffffffffu, best, o);
        int   oi = __shfl_down_sync(0xffffffffu, bidx, o);
        if (ob < best || (ob == best && oi < bidx)) { best = ob; bidx = oi; }
    }
    if (lane == 0) {
        float cx = pcs[bidx*3+0], cy = pcs[bidx*3+1], cz = pcs[bidx*3+2];
        float dx = jx - cx, dy = jy - cy, dz = jz - cz;
        float* o = att + ((size_t)hand * M1 * Jx + (size_t)bl * Jx + w) * 3;
        o[0] = expf(-50.f * dx*dx);
        o[1] = expf(-50.f * dy*dy);
        o[2] = expf(-50.f * dz*dz);
    }
}

// ---------------- concat feature assembly ----------------
__global__ void buildcat_kernel(const float* __restrict__ xl, const float* __restrict__ xr,
                                const float* __restrict__ jl, const float* __restrict__ jr,
                                const float* __restrict__ mc, const float* __restrict__ pcn,
                                const float* __restrict__ att, float* __restrict__ cat) {
    int bl = blockIdx.x, hand = blockIdx.y;
    int b = bl / Lx;
    float* dst = cat + ((size_t)hand * M1 + bl) * CATD;
    const float* xh = hand ? xr : xl;
    const float* jh = hand ? jr : jl;
    for (int c = threadIdx.x; c < CATD; c += blockDim.x) {
        float v;
        if (c < 99)        v = xh[(size_t)bl * HAND + c];
        else if (c < 162)  v = jh[(size_t)bl * 63 + (c - 99)];
        else if (c < 1186) v = mc[(size_t)b * Nx + (c - 162)];
        else if (c < 2210) v = pcn[(size_t)bl * Nx + (c - 1186)];
        else               v = att[(size_t)hand * M1 * 63 + (size_t)bl * 63 + (c - 2210)];
        dst[c] = v;
    }
}

// ---------------- tf32 helpers ----------------
__device__ __forceinline__ uint32_t f32_tf32(float x) {
    uint32_t r;
    asm("cvt.rna.tf32.f32 %0, %1;" : "=r"(r) : "f"(x));
    return r;
}
__device__ __forceinline__ void split_tf32(float v, float& h, float& l) {
    uint32_t hb = f32_tf32(v);
    h = __uint_as_float(hb);
    l = __uint_as_float(f32_tf32(v - h));
}
__device__ __forceinline__ void mma_tf32(float* c, const uint32_t* a, const uint32_t* b) {
    asm("mma.sync.aligned.m16n8k8.row.col.f32.tf32.tf32.f32 "
        "{%0,%1,%2,%3}, {%4,%5,%6,%7}, {%8,%9}, {%0,%1,%2,%3};\n"
        : "+f"(c[0]), "+f"(c[1]), "+f"(c[2]), "+f"(c[3])
        : "r"(a[0]), "r"(a[1]), "r"(a[2]), "r"(a[3]), "r"(b[0]), "r"(b[1]));
}

// ---------------- 3xTF32 tensor-core GEMM, hi/lo-interleaved smem ----------------
// Template MW = number of m-warps (2 or 4). Block tile (MW*32) x 64 x 16.
// 8 warps: MW in m, 8/MW in n. Warp tile 32 x (64/(8/MW)).
// Smem holds (hi,lo) float2 per element: one LDS.64 fetches both 3xTF32 operands.
// A: [m][k] float2, row stride 20 (conflict-free: banks 8g+2t).
// B: [k][n] float2, row stride 68 (conflict-free: banks 8t+2g).
#define ASTR 20
#define BSTR 68
#define TG_SMEM_MW(MW) ((2*(MW)*32*ASTR + 2*16*BSTR) * 8)

template<int MW>
__global__ void __launch_bounds__(256, 2)
tgemm(const float* __restrict__ A,
      const float* __restrict__ B1, const float* __restrict__ bias1,
      const float* __restrict__ B2, const float* __restrict__ bias2,
      float* __restrict__ C, int M, int N, int K, int flags, int rowsplit) {
    constexpr int TBMv = MW * 32;
    constexpr int NW   = 8 / MW;
    constexpr int WNE  = 64 / NW;      // warp n extent
    constexpr int NI   = WNE / 8;      // 4 (MW=4) or 2 (MW=2)
    constexpr int LA   = TBMv / 64;    // float4 A loads per thread (vec path)
    constexpr int SA   = TBMv / 16;    // scalar A loads per thread
    constexpr int TASZ2 = TBMv * ASTR; // float2 per A stage
    constexpr int TBSZ2 = 16 * BSTR;   // float2 per B stage

    extern __shared__ float smraw[];
    float2* As = (float2*)smraw;           // [2][TASZ2]
    float2* Bs = (float2*)smraw + 2*TASZ2; // [2][TBSZ2]

    int tid = threadIdx.x;
    int row0 = blockIdx.y * TBMv, col0 = blockIdx.x * 64;
    const float* Bw   = (row0 >= rowsplit) ? B2 : B1;
    const float* bias = (row0 >= rowsplit) ? bias2 : bias1;

    int warp = tid >> 5, lane = tid & 31;
    int wm = warp % MW, wn = warp / MW;
    int m0 = wm * 32, n0 = wn * WNE;
    int g = lane >> 2, t = lane & 3;

    float acc[2][NI][4];
    #pragma unroll
    for (int mi = 0; mi < 2; mi++)
        #pragma unroll
        for (int ni = 0; ni < NI; ni++)
            #pragma unroll
            for (int j = 0; j < 4; j++) acc[mi][ni][j] = 0.f;

    const bool vecA = ((K & 3) == 0);
    const int ntiles = (K + 15) / 16;

    float4 pa[LA];
    float  pas[SA];
    float4 pbv;
    const int b_kk = tid >> 4, b_nq = tid & 15;

    auto load_tile = [&](int ti) {
        int k0 = ti * 16;
        if (vecA) {
            #pragma unroll
            for (int i = 0; i < LA; i++) {
                int idx = tid + i*256;
                int m = idx >> 2, k4 = (idx & 3) * 4;
                pa[i] = *(const float4*)(A + (size_t)(row0 + m)*K + k0 + k4);
            }
        } else {
            #pragma unroll
            for (int i = 0; i < SA; i++) {
                int idx = tid + i*256;
                int m = idx >> 4, kk = idx & 15;
                int gk = k0 + kk;
                pas[i] = (gk < K) ? A[(size_t)(row0 + m)*K + gk] : 0.f;
            }
        }
        int gk = k0 + b_kk;
        if (gk < K) pbv = *(const float4*)(Bw + (size_t)gk*N + col0 + b_nq*4);
        else        pbv = make_float4(0.f, 0.f, 0.f, 0.f);
    };

    auto store_tile = [&](int st) {
        float2* AsS = As + st*TASZ2;
        float2* BsS = Bs + st*TBSZ2;
        if (vecA) {
            #pragma unroll
            for (int i = 0; i < LA; i++) {
                int idx = tid + i*256;
                int m = idx >> 2, k4 = (idx & 3) * 4;
                float h0,l0,h1,l1,h2,l2,h3,l3;
                split_tf32(pa[i].x, h0, l0); split_tf32(pa[i].y, h1, l1);
                split_tf32(pa[i].z, h2, l2); split_tf32(pa[i].w, h3, l3);
                float2* dst = AsS + m*ASTR + k4;
                *(float4*)(dst)     = make_float4(h0, l0, h1, l1);
                *(float4*)(dst + 2) = make_float4(h2, l2, h3, l3);
            }
        } else {
            #pragma unroll
            for (int i = 0; i < SA; i++) {
                int idx = tid + i*256;
                int m = idx >> 4, kk = idx & 15;
                float h, l;
                split_tf32(pas[i], h, l);
                AsS[m*ASTR + kk] = make_float2(h, l);
            }
        }
        {
            float h0,l0,h1,l1,h2,l2,h3,l3;
            split_tf32(pbv.x, h0, l0); split_tf32(pbv.y, h1, l1);
            split_tf32(pbv.z, h2, l2); split_tf32(pbv.w, h3, l3);
            float2* dst = BsS + b_kk*BSTR + b_nq*4;
            *(float4*)(dst)     = make_float4(h0, l0, h1, l1);
            *(float4*)(dst + 2) = make_float4(h2, l2, h3, l3);
        }
    };

    load_tile(0);
    store_tile(0);
    __syncthreads();

    for (int ti = 0; ti < ntiles; ti++) {
        int st = ti & 1;
        if (ti + 1 < ntiles) load_tile(ti + 1);

        const float2* AsS = As + st*TASZ2;
        const float2* BsS = Bs + st*TBSZ2;
        #pragma unroll
        for (int ks = 0; ks < 2; ks++) {
            int kc = ks*8 + t;
            uint32_t ahr[2][4], alr[2][4];
            #pragma unroll
            for (int mi = 0; mi < 2; mi++) {
                int mr = m0 + mi*16 + g;
                float2 p0 = AsS[mr*ASTR + kc];
                float2 p1 = AsS[(mr+8)*ASTR + kc];
                float2 p2 = AsS[mr*ASTR + kc + 4];
                float2 p3 = AsS[(mr+8)*ASTR + kc + 4];
                ahr[mi][0] = __float_as_uint(p0.x); alr[mi][0] = __float_as_uint(p0.y);
                ahr[mi][1] = __float_as_uint(p1.x); alr[mi][1] = __float_as_uint(p1.y);
                ahr[mi][2] = __float_as_uint(p2.x); alr[mi][2] = __float_as_uint(p2.y);
                ahr[mi][3] = __float_as_uint(p3.x); alr[mi][3] = __float_as_uint(p3.y);
            }
            #pragma unroll
            for (int ni = 0; ni < NI; ni++) {
                int n = n0 + ni*8 + g;
                float2 q0 = BsS[kc*BSTR + n];
                float2 q1 = BsS[(kc+4)*BSTR + n];
                uint32_t bhr[2] = {__float_as_uint(q0.x), __float_as_uint(q1.x)};
                uint32_t blr[2] = {__float_as_uint(q0.y), __float_as_uint(q1.y)};
                #pragma unroll
                for (int mi = 0; mi < 2; mi++) {
                    mma_tf32(acc[mi][ni], ahr[mi], bhr);
                    mma_tf32(acc[mi][ni], alr[mi], bhr);
                    mma_tf32(acc[mi][ni], ahr[mi], blr);
                }
            }
        }
        if (ti + 1 < ntiles) store_tile((ti + 1) & 1);
        __syncthreads();
    }

    // ---- epilogue ----
    #pragma unroll
    for (int mi = 0; mi < 2; mi++) {
        int r = row0 + m0 + mi*16 + g;
        #pragma unroll
        for (int ni = 0; ni < NI; ni++) {
            int c = col0 + n0 + ni*8 + 2*t;
            float v0 = acc[mi][ni][0], v1 = acc[mi][ni][1];
            float v2 = acc[mi][ni][2], v3 = acc[mi][ni][3];
            if (flags & 1) {
                float b0v = bias[c], b1v = bias[c+1];
                v0 += b0v; v1 += b1v; v2 += b0v; v3 += b1v;
            }
            if (flags & 2) {
                v0 = fmaxf(v0, 0.f); v1 = fmaxf(v1, 0.f);
                v2 = fmaxf(v2, 0.f); v3 = fmaxf(v3, 0.f);
            }
            C[(size_t)r*N + c]       = v0;
            C[(size_t)r*N + c + 1]   = v1;
            C[(size_t)(r+8)*N + c]   = v2;
            C[(size_t)(r+8)*N + c+1] = v3;
        }
    }
}

// ---------------- SGEMM 64x64x16 (small output heads only) ----------------
__global__ void sgemm64(const float* __restrict__ A, const float* __restrict__ Bw,
                        const float* __restrict__ bias, float* __restrict__ C,
                        int M, int N, int K, int flags) {
    __shared__ float As[16][65];
    __shared__ float Bs[16][65];
    int tid = threadIdx.x, tx = tid & 15, ty = tid >> 4;
    int row0 = blockIdx.y * 64, col0 = blockIdx.x * 64;
    float acc[4][4] = {};
    for (int k0 = 0; k0 < K; k0 += 16) {
        #pragma unroll
        for (int i = 0; i < 4; i++) {
            int idx = tid + i*256; int m = idx >> 4, kk = idx & 15;
            int gr = row0 + m, gk = k0 + kk;
            As[kk][m] = (gr < M && gk < K) ? A[(size_t)gr*K + gk] : 0.f;
        }
        #pragma unroll
        for (int i = 0; i < 4; i++) {
            int idx = tid + i*256; int kk = idx >> 6, n = idx & 63;
            int gk = k0 + kk, gc = col0 + n;
            Bs[kk][n] = (gk < K && gc < N) ? Bw[(size_t)gk*N + gc] : 0.f;
        }
        __syncthreads();
        #pragma unroll
        for (int kk = 0; kk < 16; kk++) {
            float a[4], b[4];
            #pragma unroll
            for (int i = 0; i < 4; i++) a[i] = As[kk][ty*4+i];
            #pragma unroll
            for (int j = 0; j < 4; j++) b[j] = Bs[kk][tx*4+j];
            #pragma unroll
            for (int i = 0; i < 4; i++)
                #pragma unroll
                for (int j = 0; j < 4; j++) acc[i][j] += a[i]*b[j];
        }
        __syncthreads();
    }
    #pragma unroll
    for (int i = 0; i < 4; i++) {
        int r = row0 + ty*4 + i; if (r >= M) continue;
        #pragma unroll
        for (int j = 0; j < 4; j++) {
            int c = col0 + tx*4 + j; if (c >= N) continue;
            float v = acc[i][j];
            if (flags & 1) v += bias[c];
            if (flags & 2) v = fmaxf(v, 0.f);
            C[(size_t)r*N + c] = v;
        }
    }
}

// ---------------- interleave L/R + positional encodings ----------------
__global__ void interleave_pe(const float* __restrict__ fl, const float* __restrict__ fr,
                              float* __restrict__ x) {
    int idx = blockIdx.x * blockDim.x + threadIdx.x;
    if (idx >= M2*HIDD) return;
    int d = idx & (HIDD - 1);
    int srow = idx >> 9;
    int s = srow & (SEQ - 1);
    int b = srow >> 7;
    int l = s >> 1, h = s & 1;
    const float* src = h ? fr : fl;
    float v = src[((size_t)(b*Lx + l)) * HIDD + d];
    int i2 = d & ~1;
    float div = expf((float)i2 * (-9.2103403719761836f / 512.f));
    float pl = (d & 1) ? cosf((float)l * div) : sinf((float)l * div);
    float pa = (d & 1) ? cosf((float)h * div) : sinf((float)h * div);
    x[idx] = v + pl + pa;
}

// ---------------- per-(b,h) attention ----------------
#define ATTN_SMEM ((2*SEQ*DHD + SEQ*129) * 4)
__global__ void attn_kernel(const float* __restrict__ qkv, float* __restrict__ out) {
    extern __shared__ float sm[];
    float* Ks = sm;
    float* Vs = sm + SEQ*DHD;
    float* Ss = sm + 2*SEQ*DHD;
    int b = blockIdx.x >> 3, h = blockIdx.x & 7;
    int i = threadIdx.x;
    for (int idx = i; idx < SEQ*DHD; idx += blockDim.x) {
        int s = idx >> 6, d = idx & 63;
        size_t base = ((size_t)(b*SEQ + s)) * 1536 + h*64 + d;
        Ks[idx] = qkv[base + 512];
        Vs[idx] = qkv[base + 1024];
    }
    float q[DHD];
    {
        size_t base = ((size_t)(b*SEQ + i)) * 1536 + h*64;
        #pragma unroll
        for (int d = 0; d < DHD; d++) q[d] = qkv[base + d];
    }
    __syncthreads();
    float m = -3.4e38f;
    float* srow = Ss + i*129;
    for (int k = 0; k < SEQ; k++) {
        float s = 0.f;
        #pragma unroll
        for (int d = 0; d < DHD; d++) s += q[d] * Ks[k*64 + d];
        s *= 0.125f;
        srow[k] = s;
        m = fmaxf(m, s);
    }
    float sum = 0.f;
    for (int k = 0; k < SEQ; k++) {
        float e = expf(srow[k] - m);
        srow[k] = e; sum += e;
    }
    float inv = 1.f / sum;
    size_t obase = ((size_t)(b*SEQ + i)) * HIDD + h*64;
    for (int d0 = 0; d0 < DHD; d0 += 16) {
        float acc[16] = {};
        for (int k = 0; k < SEQ; k++) {
            float p = srow[k];
            #pragma unroll
            for (int dd = 0; dd < 16; dd++) acc[dd] += p * Vs[k*64 + d0 + dd];
        }
        #pragma unroll
        for (int dd = 0; dd < 16; dd++) out[obase + d0 + dd] = acc[dd] * inv;
    }
}

// ---------------- residual + layernorm ----------------
__global__ void addln_kernel(const float* __restrict__ a, const float* __restrict__ r,
                             const float* __restrict__ g, const float* __restrict__ be,
                             float* __restrict__ out) {
    int row = blockIdx.x;
    int t = threadIdx.x;
    const float* pa = a + (size_t)row * HIDD;
    const float* pr = r + (size_t)row * HIDD;
    float v[4];
    #pragma unroll
    for (int i = 0; i < 4; i++) { int c = t + i*128; v[i] = pa[c] + pr[c]; }
    float s = v[0] + v[1] + v[2] + v[3];
    __shared__ float sh[4];
    for (int o = 16; o; o >>= 1) s += __shfl_down_sync(0xffffffffu, s, o);
    int lane = t & 31, w = t >> 5;
    if (lane == 0) sh[w] = s;
    __syncthreads();
    float mu = (sh[0] + sh[1] + sh[2] + sh[3]) * (1.f / HIDD);
    float qv = 0.f;
    #pragma unroll
    for (int i = 0; i < 4; i++) { float d = v[i] - mu; qv += d*d; }
    __syncthreads();
    for (int o = 16; o; o >>= 1) qv += __shfl_down_sync(0xffffffffu, qv, o);
    if (lane == 0) sh[w] = qv;
    __syncthreads();
    float var = (sh[0] + sh[1] + sh[2] + sh[3]) * (1.f / HIDD);
    float inv = rsqrtf(var + 1e-5f);
    float* po = out + (size_t)row * HIDD;
    #pragma unroll
    for (int i = 0; i < 4; i++) { int c = t + i*128; po[c] = (v[i] - mu)*inv*g[c] + be[c]; }
}

// ---------------- deinterleave even/odd rows ----------------
__global__ void deinterleave(const float* __restrict__ x,
                             float* __restrict__ fl, float* __restrict__ fr) {
    int idx = blockIdx.x * blockDim.x + threadIdx.x;
    if (idx >= M1*HIDD) return;
    int d = idx & 511; int bl = idx >> 9;
    int b = bl >> 6, l = bl & 63;
    fl[idx] = x[((size_t)(b*SEQ + 2*l    )) * HIDD + d];
    fr[idx] = x[((size_t)(b*SEQ + 2*l + 1)) * HIDD + d];
}

// ---------------- launch ----------------
extern "C" void kernel_launch(void* const* d_in, const int* in_sizes, int n_in,
                              void* d_out, int out_size) {
    const float* x_lhand     = (const float*)d_in[0];
    const float* x_rhand     = (const float*)d_in[1];
    const float* j_lhand     = (const float*)d_in[2];
    const float* j_rhand     = (const float*)d_in[3];
    const float* m_contact   = (const float*)d_in[4];
    const float* x_obj       = (const float*)d_in[5];
    const float* point_cloud = (const float*)d_in[6];
    const float* fc_lw  = (const float*)d_in[7];
    const float* fc_lb  = (const float*)d_in[8];
    const float* fc_rw  = (const float*)d_in[9];
    const float* fc_rb  = (const float*)d_in[10];
    const float* out_lw = (const float*)d_in[11];
    const float* out_lb = (const float*)d_in[12];
    const float* out_rw = (const float*)d_in[13];
    const float* out_rb = (const float*)d_in[14];
    const float* Wqkv   = (const float*)d_in[15];
    const float* bqkv   = (const float*)d_in[16];
    const float* Wo     = (const float*)d_in[17];
    const float* bo     = (const float*)d_in[18];
    const float* W1     = (const float*)d_in[19];
    const float* b1f    = (const float*)d_in[20];
    const float* W2     = (const float*)d_in[21];
    const float* b2f    = (const float*)d_in[22];
    const float* ln1_g  = (const float*)d_in[23];
    const float* ln1_b  = (const float*)d_in[24];
    const float* ln2_g  = (const float*)d_in[25];
    const float* ln2_b  = (const float*)d_in[26];
    float* out = (float*)d_out;

    float* base = nullptr;
    cudaGetSymbolAddress((void**)&base, g_scratch);
    float* pct = base + OFF_PCT;
    float* pcn = base + OFF_PCN;
    float* att = base + OFF_ATT;
    float* cat = base + OFF_CAT;
    float* fcb = base + OFF_FC;
    float* x   = base + OFF_X;
    float* h   = base + OFF_H;
    float* qkv = base + OFF_QKV;
    float* ao  = base + OFF_AO;
    float* ff  = base + OFF_FF;
    float* tmp = base + OFF_TMP;

    cudaFuncSetAttribute(attn_kernel, cudaFuncAttributeMaxDynamicSharedMemorySize, ATTN_SMEM);
    cudaFuncSetAttribute(tgemm<2>, cudaFuncAttributeMaxDynamicSharedMemorySize, TG_SMEM_MW(2));
    cudaFuncSetAttribute(tgemm<4>, cudaFuncAttributeMaxDynamicSharedMemorySize, TG_SMEM_MW(4));

    transform_kernel<<<M1, 256>>>(x_obj, point_cloud, pct, pcn);
    attmap_kernel<<<dim3(M1, 2), Jx*32>>>(j_lhand, j_rhand, pct, att);
    buildcat_kernel<<<dim3(M1, 2), 256>>>(x_lhand, x_rhand, j_lhand, j_rhand,
                                          m_contact, pcn, att, cat);

    // fused both-hand input projection: [2048 x 2273] @ [2273 x 512], row-split weights
    tgemm<2><<<dim3(8, 32), 256, TG_SMEM_MW(2)>>>(cat, fc_lw, fc_lb, fc_rw, fc_rb,
                                                  fcb, 2*M1, HIDD, CATD, 1, M1);
    interleave_pe<<<(M2*HIDD + 255)/256, 256>>>(fcb, fcb + M1*HIDD, x);

    for (int l = 0; l < NLAYERS; l++) {
        const float* wq = Wqkv + (size_t)l*HIDD*3*HIDD;
        const float* bq = bqkv + (size_t)l*3*HIDD;
        tgemm<4><<<dim3(24, 16), 256, TG_SMEM_MW(4)>>>(x, wq, bq, wq, bq,
                                                       qkv, M2, 3*HIDD, HIDD, 1, M2);
        attn_kernel<<<Bx*NHEADS, SEQ, ATTN_SMEM>>>(qkv, ao);
        const float* wo = Wo + (size_t)l*HIDD*HIDD;
        const float* bob = bo + (size_t)l*HIDD;
        tgemm<2><<<dim3(8, 32), 256, TG_SMEM_MW(2)>>>(ao, wo, bob, wo, bob,
                                                      tmp, M2, HIDD, HIDD, 1, M2);
        addln_kernel<<<M2, 128>>>(x, tmp, ln1_g + (size_t)l*HIDD, ln1_b + (size_t)l*HIDD, h);
        const float* w1 = W1 + (size_t)l*HIDD*4*HIDD;
        const float* b1 = b1f + (size_t)l*4*HIDD;
        tgemm<4><<<dim3(32, 16), 256, TG_SMEM_MW(4)>>>(h, w1, b1, w1, b1,
                                                       ff, M2, 4*HIDD, HIDD, 1 | 2, M2);
        const float* w2 = W2 + (size_t)l*4*HIDD*HIDD;
        const float* b2 = b2f + (size_t)l*HIDD;
        tgemm<2><<<dim3(8, 32), 256, TG_SMEM_MW(2)>>>(ff, w2, b2, w2, b2,
                                                      tmp, M2, HIDD, 4*HIDD, 1, M2);
        addln_kernel<<<M2, 128>>>(h, tmp, ln2_g + (size_t)l*HIDD, ln2_b + (size_t)l*HIDD, x);
    }

    deinterleave<<<(M1*HIDD + 255)/256, 256>>>(x, fcb, fcb + M1*HIDD);
    sgemm64<<<dim3(2, 16), 256>>>(fcb,           out_lw, out_lb, out,           M1, HAND, HIDD, 1);
    sgemm64<<<dim3(2, 16), 256>>>(fcb + M1*HIDD, out_rw, out_rb, out + M1*HAND, M1, HAND, HIDD, 1);
}

// round 7
// speedup vs baseline: 1.8388x; 1.8388x over previous
#include <cuda_runtime.h>
#include <cuda_bf16.h>
#include <math.h>
#include <stdint.h>

// ---------------- problem constants ----------------
#define Bx      16
#define Lx      64
#define Nx      1024
#define HAND    99
#define Jx      21
#define HIDD    512
#define NLAYERS 4
#define NHEADS  8
#define DHD     64
#define CATD    2273
#define SEQ     128          // 2*Lx
#define M1      (Bx*Lx)      // 1024 rows per hand
#define M2      (Bx*SEQ)     // 2048 transformer rows

// ---------------- scratch (single __device__ arena) ----------------
#define OFF_PCT   0
#define SZ_PCT    (M1*Nx*3)
#define OFF_PCN   (OFF_PCT + SZ_PCT)
#define SZ_PCN    (M1*Nx)
#define OFF_ATT   (OFF_PCN + SZ_PCN)
#define SZ_ATT    (2*M1*Jx*3)
#define OFF_CAT   (OFF_ATT + SZ_ATT)
#define SZ_CAT    (2*M1*CATD)
#define OFF_FC    (OFF_CAT + SZ_CAT)
#define SZ_FC     (2*M1*HIDD)
#define OFF_X     (OFF_FC + SZ_FC)
#define SZ_X      (M2*HIDD)
#define OFF_H     (OFF_X + SZ_X)
#define SZ_H      (M2*HIDD)
#define OFF_QKV   (OFF_H + SZ_H)
#define SZ_QKV    (M2*3*HIDD)
#define OFF_AO    (OFF_QKV + SZ_QKV)
#define SZ_AO     (M2*HIDD)
#define OFF_FF    (OFF_AO + SZ_AO)
#define SZ_FF     (M2*4*HIDD)
#define OFF_TMP   (OFF_FF + SZ_FF)
#define SZ_TMP    (M2*HIDD)
#define SCRATCH_TOTAL (OFF_TMP + SZ_TMP)

__device__ float g_scratch[SCRATCH_TOTAL];

// ---------------- rot6d + pc transform + norm ----------------
__global__ void transform_kernel(const float* __restrict__ x_obj,
                                 const float* __restrict__ pc,
                                 float* __restrict__ pct,
                                 float* __restrict__ pcn) {
    int bl = blockIdx.x;
    int b  = bl / Lx;
    const float* xo = x_obj + (size_t)bl * 10;
    float tx = xo[0], ty = xo[1], tz = xo[2];
    float a1x = xo[3], a1y = xo[4], a1z = xo[5];
    float a2x = xo[6], a2y = xo[7], a2z = xo[8];
    float n1 = sqrtf(a1x*a1x + a1y*a1y + a1z*a1z);
    float b1x = a1x/n1, b1y = a1y/n1, b1z = a1z/n1;
    float dd  = b1x*a2x + b1y*a2y + b1z*a2z;
    float b2x = a2x - dd*b1x, b2y = a2y - dd*b1y, b2z = a2z - dd*b1z;
    float n2 = sqrtf(b2x*b2x + b2y*b2y + b2z*b2z);
    b2x /= n2; b2y /= n2; b2z /= n2;
    float b3x = b1y*b2z - b1z*b2y;
    float b3y = b1z*b2x - b1x*b2z;
    float b3z = b1x*b2y - b1y*b2x;
    const float* pcb = pc + (size_t)b * Nx * 3;
    for (int n = threadIdx.x; n < Nx; n += blockDim.x) {
        float px = pcb[n*3+0], py = pcb[n*3+1], pz = pcb[n*3+2];
        float ox = b1x*px + b2x*py + b3x*pz + tx;
        float oy = b1y*px + b2y*py + b3y*pz + ty;
        float oz = b1z*px + b2z*py + b3z*pz + tz;
        float* o = pct + ((size_t)bl * Nx + n) * 3;
        o[0] = ox; o[1] = oy; o[2] = oz;
        pcn[(size_t)bl * Nx + n] = sqrtf(ox*ox + oy*oy + oz*oz);
    }
}

// ---------------- nearest-point attention map ----------------
__global__ void attmap_kernel(const float* __restrict__ jl,
                              const float* __restrict__ jr,
                              const float* __restrict__ pct,
                              float* __restrict__ att) {
    __shared__ float pcs[Nx*3];
    int bl = blockIdx.x, hand = blockIdx.y;
    const float* src = pct + (size_t)bl * Nx * 3;
    for (int i = threadIdx.x; i < Nx*3; i += blockDim.x) pcs[i] = src[i];
    __syncthreads();
    int w = threadIdx.x >> 5, lane = threadIdx.x & 31;
    if (w >= Jx) return;
    const float* jp = (hand ? jr : jl) + ((size_t)bl * Jx + w) * 3;
    float jx = jp[0], jy = jp[1], jz = jp[2];
    float jj = jx*jx + jy*jy + jz*jz;
    float best = 3.4e38f; int bidx = Nx;
    for (int n = lane; n < Nx; n += 32) {
        float px = pcs[n*3+0], py = pcs[n*3+1], pz = pcs[n*3+2];
        float pp = px*px + py*py + pz*pz;
        float d2 = jj + pp - 2.f*(jx*px + jy*py + jz*pz);
        if (d2 < best || (d2 == best && n < bidx)) { best = d2; bidx = n; }
    }
    for (int o = 16; o; o >>= 1) {
        float ob = __shfl_down_sync(0xffffffffu, best, o);
        int   oi = __shfl_down_sync(0xffffffffu, bidx, o);
        if (ob < best || (ob == best && oi < bidx)) { best = ob; bidx = oi; }
    }
    if (lane == 0) {
        float cx = pcs[bidx*3+0], cy = pcs[bidx*3+1], cz = pcs[bidx*3+2];
        float dx = jx - cx, dy = jy - cy, dz = jz - cz;
        float* o = att + ((size_t)hand * M1 * Jx + (size_t)bl * Jx + w) * 3;
        o[0] = expf(-50.f * dx*dx);
        o[1] = expf(-50.f * dy*dy);
        o[2] = expf(-50.f * dz*dz);
    }
}

// ---------------- concat feature assembly ----------------
__global__ void buildcat_kernel(const float* __restrict__ xl, const float* __restrict__ xr,
                                const float* __restrict__ jl, const float* __restrict__ jr,
                                const float* __restrict__ mc, const float* __restrict__ pcn,
                                const float* __restrict__ att, float* __restrict__ cat) {
    int bl = blockIdx.x, hand = blockIdx.y;
    int b = bl / Lx;
    float* dst = cat + ((size_t)hand * M1 + bl) * CATD;
    const float* xh = hand ? xr : xl;
    const float* jh = hand ? jr : jl;
    for (int c = threadIdx.x; c < CATD; c += blockDim.x) {
        float v;
        if (c < 99)        v = xh[(size_t)bl * HAND + c];
        else if (c < 162)  v = jh[(size_t)bl * 63 + (c - 99)];
        else if (c < 1186) v = mc[(size_t)b * Nx + (c - 162)];
        else if (c < 2210) v = pcn[(size_t)bl * Nx + (c - 1186)];
        else               v = att[(size_t)hand * M1 * 63 + (size_t)bl * 63 + (c - 2210)];
        dst[c] = v;
    }
}

// ---------------- bf16 helpers ----------------
// pack two floats as bf16x2 word: 'e' (k even) -> low half, 'o' (k odd) -> high half
__device__ __forceinline__ uint32_t pack_bf16(float e, float o) {
    uint32_t r;
    asm("cvt.rn.bf16x2.f32 %0, %1, %2;" : "=r"(r) : "f"(o), "f"(e));
    return r;
}
// exact bf16 -> f32 of both halves
__device__ __forceinline__ float2 unpack_bf16(uint32_t w) {
    float2 f;
    f.x = __uint_as_float(w << 16);
    f.y = __uint_as_float(w & 0xffff0000u);
    return f;
}
// split (e,o) into hi word + residual-lo word
__device__ __forceinline__ void split_pair(float e, float o, uint32_t& hw, uint32_t& lw) {
    hw = pack_bf16(e, o);
    float2 hf = unpack_bf16(hw);
    lw = pack_bf16(e - hf.x, o - hf.y);
}
__device__ __forceinline__ void mma_bf16(float* c, const uint32_t* a, const uint32_t* b) {
    asm("mma.sync.aligned.m16n8k16.row.col.f32.bf16.bf16.f32 "
        "{%0,%1,%2,%3}, {%4,%5,%6,%7}, {%8,%9}, {%0,%1,%2,%3};\n"
        : "+f"(c[0]), "+f"(c[1]), "+f"(c[2]), "+f"(c[3])
        : "r"(a[0]), "r"(a[1]), "r"(a[2]), "r"(a[3]), "r"(b[0]), "r"(b[1]));
}

// ---------------- bf16x3 tensor-core GEMM (m16n8k16), double-buffered ----------------
// Block tile 128x64x32, 8 warps (4m x 2n), warp tile 32x32.
// Smem words pack 2 k-elements (bf16x2). hi and lo arrays separate.
// A: [m][kw] word stride 20 (banks 20m+kw distinct). kw = k/2, 16 words per row.
// B: [kw][n] word stride 72 (banks 72kw+n -> 8t+g distinct).
#define TBM 128
#define TBN 64
#define TBK 32
#define AST 20
#define BST 72
#define TASZ (TBM*AST)        // 2560 words per copy
#define TBSZ (16*BST)         // 1152 words per copy
#define TG_SMEM ((4*TASZ + 4*TBSZ) * 4)  // 2 stages * (hi+lo) = 59392 B

__global__ void __launch_bounds__(256, 2)
tgemm(const float* __restrict__ A,
      const float* __restrict__ B1, const float* __restrict__ bias1,
      const float* __restrict__ B2, const float* __restrict__ bias2,
      float* __restrict__ C, int M, int N, int K, int flags, int rowsplit) {
    extern __shared__ uint32_t smw[];
    uint32_t* Ah = smw;                    // [2][TASZ]
    uint32_t* Al = Ah + 2*TASZ;
    uint32_t* Bh = Al + 2*TASZ;            // [2][TBSZ]
    uint32_t* Bl = Bh + 2*TBSZ;

    int tid = threadIdx.x;
    int row0 = blockIdx.y * TBM, col0 = blockIdx.x * TBN;
    const float* Bw   = (row0 >= rowsplit) ? B2 : B1;
    const float* bias = (row0 >= rowsplit) ? bias2 : bias1;

    int warp = tid >> 5, lane = tid & 31;
    int wm = warp & 3, wn = warp >> 2;
    int m0 = wm * 32, n0 = wn * 32;
    int g = lane >> 2, t = lane & 3;

    float acc[2][4][4];
    #pragma unroll
    for (int mi = 0; mi < 2; mi++)
        #pragma unroll
        for (int ni = 0; ni < 4; ni++)
            #pragma unroll
            for (int j = 0; j < 4; j++) acc[mi][ni][j] = 0.f;

    const bool vecA = ((K & 3) == 0);
    const int ntiles = (K + TBK - 1) / TBK;

    // prefetch registers
    float4 pa[4];                // vec path: 4 float4 (TBM*TBK/256/4)
    float  pas[16];              // scalar path: 8 word-pairs
    float4 pb0, pb1;             // B: two k-rows, 4 n each

    const int a_m  = tid >> 3,  a_k4 = (tid & 7) * 4;   // vec path ids (idx = tid + i*256 -> m += 32*i)
    const int b_kp = tid >> 4,  b_nq = tid & 15;        // B: k-pair 0..15, n-quad 0..15

    auto load_tile = [&](int ti) {
        int k0 = ti * TBK;
        if (vecA) {
            #pragma unroll
            for (int i = 0; i < 4; i++) {
                int m = a_m + i*32;
                int gk = k0 + a_k4;
                if (gk < K) pa[i] = *(const float4*)(A + (size_t)(row0 + m)*K + gk);
                else        pa[i] = make_float4(0.f,0.f,0.f,0.f);
            }
        } else {
            #pragma unroll
            for (int i = 0; i < 8; i++) {
                int idx = tid + i*256;
                int m = idx >> 4, kw = idx & 15;
                int gk = k0 + kw*2;
                pas[2*i]   = (gk     < K) ? A[(size_t)(row0 + m)*K + gk]     : 0.f;
                pas[2*i+1] = (gk + 1 < K) ? A[(size_t)(row0 + m)*K + gk + 1] : 0.f;
            }
        }
        int gk0 = k0 + 2*b_kp, gk1 = gk0 + 1;
        if (gk0 < K) pb0 = *(const float4*)(Bw + (size_t)gk0*N + col0 + b_nq*4);
        else         pb0 = make_float4(0.f,0.f,0.f,0.f);
        if (gk1 < K) pb1 = *(const float4*)(Bw + (size_t)gk1*N + col0 + b_nq*4);
        else         pb1 = make_float4(0.f,0.f,0.f,0.f);
    };

    auto store_tile = [&](int st) {
        uint32_t* AhS = Ah + st*TASZ; uint32_t* AlS = Al + st*TASZ;
        uint32_t* BhS = Bh + st*TBSZ; uint32_t* BlS = Bl + st*TBSZ;
        if (vecA) {
            #pragma unroll
            for (int i = 0; i < 4; i++) {
                int m = a_m + i*32;
                int kw0 = a_k4 >> 1;            // even
                uint32_t h0,l0,h1,l1;
                split_pair(pa[i].x, pa[i].y, h0, l0);
                split_pair(pa[i].z, pa[i].w, h1, l1);
                *(uint2*)(AhS + m*AST + kw0) = make_uint2(h0, h1);
                *(uint2*)(AlS + m*AST + kw0) = make_uint2(l0, l1);
            }
        } else {
            #pragma unroll
            for (int i = 0; i < 8; i++) {
                int idx = tid + i*256;
                int m = idx >> 4, kw = idx & 15;
                uint32_t hw, lw;
                split_pair(pas[2*i], pas[2*i+1], hw, lw);
                AhS[m*AST + kw] = hw;
                AlS[m*AST + kw] = lw;
            }
        }
        {
            uint32_t hw[4], lw[4];
            split_pair(pb0.x, pb1.x, hw[0], lw[0]);
            split_pair(pb0.y, pb1.y, hw[1], lw[1]);
            split_pair(pb0.z, pb1.z, hw[2], lw[2]);
            split_pair(pb0.w, pb1.w, hw[3], lw[3]);
            *(uint4*)(BhS + b_kp*BST + b_nq*4) = make_uint4(hw[0],hw[1],hw[2],hw[3]);
            *(uint4*)(BlS + b_kp*BST + b_nq*4) = make_uint4(lw[0],lw[1],lw[2],lw[3]);
        }
    };

    load_tile(0);
    store_tile(0);
    __syncthreads();

    for (int ti = 0; ti < ntiles; ti++) {
        int st = ti & 1;
        if (ti + 1 < ntiles) load_tile(ti + 1);

        const uint32_t* AhS = Ah + st*TASZ; const uint32_t* AlS = Al + st*TASZ;
        const uint32_t* BhS = Bh + st*TBSZ; const uint32_t* BlS = Bl + st*TBSZ;
        #pragma unroll
        for (int ks = 0; ks < 2; ks++) {
            int kw = ks*8 + t;
            uint32_t ahr[2][4], alr[2][4];
            #pragma unroll
            for (int mi = 0; mi < 2; mi++) {
                int mr = m0 + mi*16 + g;
                ahr[mi][0] = AhS[mr*AST + kw];
                ahr[mi][1] = AhS[(mr+8)*AST + kw];
                ahr[mi][2] = AhS[mr*AST + kw + 4];
                ahr[mi][3] = AhS[(mr+8)*AST + kw + 4];
                alr[mi][0] = AlS[mr*AST + kw];
                alr[mi][1] = AlS[(mr+8)*AST + kw];
                alr[mi][2] = AlS[mr*AST + kw + 4];
                alr[mi][3] = AlS[(mr+8)*AST + kw + 4];
            }
            #pragma unroll
            for (int ni = 0; ni < 4; ni++) {
                int n = n0 + ni*8 + g;
                uint32_t bhr[2], blr[2];
                bhr[0] = BhS[kw*BST + n];
                bhr[1] = BhS[(kw+4)*BST + n];
                blr[0] = BlS[kw*BST + n];
                blr[1] = BlS[(kw+4)*BST + n];
                #pragma unroll
                for (int mi = 0; mi < 2; mi++) {
                    mma_bf16(acc[mi][ni], ahr[mi], bhr);
                    mma_bf16(acc[mi][ni], alr[mi], bhr);
                    mma_bf16(acc[mi][ni], ahr[mi], blr);
                }
            }
        }
        if (ti + 1 < ntiles) store_tile((ti + 1) & 1);
        __syncthreads();
    }

    // ---- epilogue ----
    #pragma unroll
    for (int mi = 0; mi < 2; mi++) {
        int r = row0 + m0 + mi*16 + g;
        #pragma unroll
        for (int ni = 0; ni < 4; ni++) {
            int c = col0 + n0 + ni*8 + 2*t;
            float v0 = acc[mi][ni][0], v1 = acc[mi][ni][1];
            float v2 = acc[mi][ni][2], v3 = acc[mi][ni][3];
            if (flags & 1) {
                float b0v = bias[c], b1v = bias[c+1];
                v0 += b0v; v1 += b1v; v2 += b0v; v3 += b1v;
            }
            if (flags & 2) {
                v0 = fmaxf(v0, 0.f); v1 = fmaxf(v1, 0.f);
                v2 = fmaxf(v2, 0.f); v3 = fmaxf(v3, 0.f);
            }
            C[(size_t)r*N + c]       = v0;
            C[(size_t)r*N + c + 1]   = v1;
            C[(size_t)(r+8)*N + c]   = v2;
            C[(size_t)(r+8)*N + c+1] = v3;
        }
    }
}

// ---------------- SGEMM 64x64x16 (small output heads only) ----------------
__global__ void sgemm64(const float* __restrict__ A, const float* __restrict__ Bw,
                        const float* __restrict__ bias, float* __restrict__ C,
                        int M, int N, int K, int flags) {
    __shared__ float As[16][65];
    __shared__ float Bs[16][65];
    int tid = threadIdx.x, tx = tid & 15, ty = tid >> 4;
    int row0 = blockIdx.y * 64, col0 = blockIdx.x * 64;
    float acc[4][4] = {};
    for (int k0 = 0; k0 < K; k0 += 16) {
        #pragma unroll
        for (int i = 0; i < 4; i++) {
            int idx = tid + i*256; int m = idx >> 4, kk = idx & 15;
            int gr = row0 + m, gk = k0 + kk;
            As[kk][m] = (gr < M && gk < K) ? A[(size_t)gr*K + gk] : 0.f;
        }
        #pragma unroll
        for (int i = 0; i < 4; i++) {
            int idx = tid + i*256; int kk = idx >> 6, n = idx & 63;
            int gk = k0 + kk, gc = col0 + n;
            Bs[kk][n] = (gk < K && gc < N) ? Bw[(size_t)gk*N + gc] : 0.f;
        }
        __syncthreads();
        #pragma unroll
        for (int kk = 0; kk < 16; kk++) {
            float a[4], b[4];
            #pragma unroll
            for (int i = 0; i < 4; i++) a[i] = As[kk][ty*4+i];
            #pragma unroll
            for (int j = 0; j < 4; j++) b[j] = Bs[kk][tx*4+j];
            #pragma unroll
            for (int i = 0; i < 4; i++)
                #pragma unroll
                for (int j = 0; j < 4; j++) acc[i][j] += a[i]*b[j];
        }
        __syncthreads();
    }
    #pragma unroll
    for (int i = 0; i < 4; i++) {
        int r = row0 + ty*4 + i; if (r >= M) continue;
        #pragma unroll
        for (int j = 0; j < 4; j++) {
            int c = col0 + tx*4 + j; if (c >= N) continue;
            float v = acc[i][j];
            if (flags & 1) v += bias[c];
            if (flags & 2) v = fmaxf(v, 0.f);
            C[(size_t)r*N + c] = v;
        }
    }
}

// ---------------- interleave L/R + positional encodings ----------------
__global__ void interleave_pe(const float* __restrict__ fl, const float* __restrict__ fr,
                              float* __restrict__ x) {
    int idx = blockIdx.x * blockDim.x + threadIdx.x;
    if (idx >= M2*HIDD) return;
    int d = idx & (HIDD - 1);
    int srow = idx >> 9;
    int s = srow & (SEQ - 1);
    int b = srow >> 7;
    int l = s >> 1, h = s & 1;
    const float* src = h ? fr : fl;
    float v = src[((size_t)(b*Lx + l)) * HIDD + d];
    int i2 = d & ~1;
    float div = expf((float)i2 * (-9.2103403719761836f / 512.f));
    float pl = (d & 1) ? cosf((float)l * div) : sinf((float)l * div);
    float pa = (d & 1) ? cosf((float)h * div) : sinf((float)h * div);
    x[idx] = v + pl + pa;
}

// ---------------- per-(b,h) attention ----------------
#define ATTN_SMEM ((2*SEQ*DHD + SEQ*129) * 4)
__global__ void attn_kernel(const float* __restrict__ qkv, float* __restrict__ out) {
    extern __shared__ float sm[];
    float* Ks = sm;
    float* Vs = sm + SEQ*DHD;
    float* Ss = sm + 2*SEQ*DHD;
    int b = blockIdx.x >> 3, h = blockIdx.x & 7;
    int i = threadIdx.x;
    for (int idx = i; idx < SEQ*DHD; idx += blockDim.x) {
        int s = idx >> 6, d = idx & 63;
        size_t base = ((size_t)(b*SEQ + s)) * 1536 + h*64 + d;
        Ks[idx] = qkv[base + 512];
        Vs[idx] = qkv[base + 1024];
    }
    float q[DHD];
    {
        size_t base = ((size_t)(b*SEQ + i)) * 1536 + h*64;
        #pragma unroll
        for (int d = 0; d < DHD; d++) q[d] = qkv[base + d];
    }
    __syncthreads();
    float m = -3.4e38f;
    float* srow = Ss + i*129;
    for (int k = 0; k < SEQ; k++) {
        float s = 0.f;
        #pragma unroll
        for (int d = 0; d < DHD; d++) s += q[d] * Ks[k*64 + d];
        s *= 0.125f;
        srow[k] = s;
        m = fmaxf(m, s);
    }
    float sum = 0.f;
    for (int k = 0; k < SEQ; k++) {
        float e = expf(srow[k] - m);
        srow[k] = e; sum += e;
    }
    float inv = 1.f / sum;
    size_t obase = ((size_t)(b*SEQ + i)) * HIDD + h*64;
    for (int d0 = 0; d0 < DHD; d0 += 16) {
        float acc[16] = {};
        for (int k = 0; k < SEQ; k++) {
            float p = srow[k];
            #pragma unroll
            for (int dd = 0; dd < 16; dd++) acc[dd] += p * Vs[k*64 + d0 + dd];
        }
        #pragma unroll
        for (int dd = 0; dd < 16; dd++) out[obase + d0 + dd] = acc[dd] * inv;
    }
}

// ---------------- residual + layernorm ----------------
__global__ void addln_kernel(const float* __restrict__ a, const float* __restrict__ r,
                             const float* __restrict__ g, const float* __restrict__ be,
                             float* __restrict__ out) {
    int row = blockIdx.x;
    int t = threadIdx.x;
    const float* pa = a + (size_t)row * HIDD;
    const float* pr = r + (size_t)row * HIDD;
    float v[4];
    #pragma unroll
    for (int i = 0; i < 4; i++) { int c = t + i*128; v[i] = pa[c] + pr[c]; }
    float s = v[0] + v[1] + v[2] + v[3];
    __shared__ float sh[4];
    for (int o = 16; o; o >>= 1) s += __shfl_down_sync(0xffffffffu, s, o);
    int lane = t & 31, w = t >> 5;
    if (lane == 0) sh[w] = s;
    __syncthreads();
    float mu = (sh[0] + sh[1] + sh[2] + sh[3]) * (1.f / HIDD);
    float qv = 0.f;
    #pragma unroll
    for (int i = 0; i < 4; i++) { float d = v[i] - mu; qv += d*d; }
    __syncthreads();
    for (int o = 16; o; o >>= 1) qv += __shfl_down_sync(0xffffffffu, qv, o);
    if (lane == 0) sh[w] = qv;
    __syncthreads();
    float var = (sh[0] + sh[1] + sh[2] + sh[3]) * (1.f / HIDD);
    float inv = rsqrtf(var + 1e-5f);
    float* po = out + (size_t)row * HIDD;
    #pragma unroll
    for (int i = 0; i < 4; i++) { int c = t + i*128; po[c] = (v[i] - mu)*inv*g[c] + be[c]; }
}

// ---------------- deinterleave even/odd rows ----------------
__global__ void deinterleave(const float* __restrict__ x,
                             float* __restrict__ fl, float* __restrict__ fr) {
    int idx = blockIdx.x * blockDim.x + threadIdx.x;
    if (idx >= M1*HIDD) return;
    int d = idx & 511; int bl = idx >> 9;
    int b = bl >> 6, l = bl & 63;
    fl[idx] = x[((size_t)(b*SEQ + 2*l    )) * HIDD + d];
    fr[idx] = x[((size_t)(b*SEQ + 2*l + 1)) * HIDD + d];
}

// ---------------- launch ----------------
extern "C" void kernel_launch(void* const* d_in, const int* in_sizes, int n_in,
                              void* d_out, int out_size) {
    const float* x_lhand     = (const float*)d_in[0];
    const float* x_rhand     = (const float*)d_in[1];
    const float* j_lhand     = (const float*)d_in[2];
    const float* j_rhand     = (const float*)d_in[3];
    const float* m_contact   = (const float*)d_in[4];
    const float* x_obj       = (const float*)d_in[5];
    const float* point_cloud = (const float*)d_in[6];
    const float* fc_lw  = (const float*)d_in[7];
    const float* fc_lb  = (const float*)d_in[8];
    const float* fc_rw  = (const float*)d_in[9];
    const float* fc_rb  = (const float*)d_in[10];
    const float* out_lw = (const float*)d_in[11];
    const float* out_lb = (const float*)d_in[12];
    const float* out_rw = (const float*)d_in[13];
    const float* out_rb = (const float*)d_in[14];
    const float* Wqkv   = (const float*)d_in[15];
    const float* bqkv   = (const float*)d_in[16];
    const float* Wo     = (const float*)d_in[17];
    const float* bo     = (const float*)d_in[18];
    const float* W1     = (const float*)d_in[19];
    const float* b1f    = (const float*)d_in[20];
    const float* W2     = (const float*)d_in[21];
    const float* b2f    = (const float*)d_in[22];
    const float* ln1_g  = (const float*)d_in[23];
    const float* ln1_b  = (const float*)d_in[24];
    const float* ln2_g  = (const float*)d_in[25];
    const float* ln2_b  = (const float*)d_in[26];
    float* out = (float*)d_out;

    float* base = nullptr;
    cudaGetSymbolAddress((void**)&base, g_scratch);
    float* pct = base + OFF_PCT;
    float* pcn = base + OFF_PCN;
    float* att = base + OFF_ATT;
    float* cat = base + OFF_CAT;
    float* fcb = base + OFF_FC;
    float* x   = base + OFF_X;
    float* h   = base + OFF_H;
    float* qkv = base + OFF_QKV;
    float* ao  = base + OFF_AO;
    float* ff  = base + OFF_FF;
    float* tmp = base + OFF_TMP;

    cudaFuncSetAttribute(attn_kernel, cudaFuncAttributeMaxDynamicSharedMemorySize, ATTN_SMEM);
    cudaFuncSetAttribute(tgemm, cudaFuncAttributeMaxDynamicSharedMemorySize, TG_SMEM);

    transform_kernel<<<M1, 256>>>(x_obj, point_cloud, pct, pcn);
    attmap_kernel<<<dim3(M1, 2), Jx*32>>>(j_lhand, j_rhand, pct, att);
    buildcat_kernel<<<dim3(M1, 2), 256>>>(x_lhand, x_rhand, j_lhand, j_rhand,
                                          m_contact, pcn, att, cat);

    // fused both-hand input projection: [2048 x 2273] @ [2273 x 512], row-split weights
    tgemm<<<dim3(8, 16), 256, TG_SMEM>>>(cat, fc_lw, fc_lb, fc_rw, fc_rb,
                                         fcb, 2*M1, HIDD, CATD, 1, M1);
    interleave_pe<<<(M2*HIDD + 255)/256, 256>>>(fcb, fcb + M1*HIDD, x);

    for (int l = 0; l < NLAYERS; l++) {
        const float* wq = Wqkv + (size_t)l*HIDD*3*HIDD;
        const float* bq = bqkv + (size_t)l*3*HIDD;
        tgemm<<<dim3(24, 16), 256, TG_SMEM>>>(x, wq, bq, wq, bq,
                                              qkv, M2, 3*HIDD, HIDD, 1, M2);
        attn_kernel<<<Bx*NHEADS, SEQ, ATTN_SMEM>>>(qkv, ao);
        const float* wo = Wo + (size_t)l*HIDD*HIDD;
        const float* bob = bo + (size_t)l*HIDD;
        tgemm<<<dim3(8, 16), 256, TG_SMEM>>>(ao, wo, bob, wo, bob,
                                             tmp, M2, HIDD, HIDD, 1, M2);
        addln_kernel<<<M2, 128>>>(x, tmp, ln1_g + (size_t)l*HIDD, ln1_b + (size_t)l*HIDD, h);
        const float* w1 = W1 + (size_t)l*HIDD*4*HIDD;
        const float* b1 = b1f + (size_t)l*4*HIDD;
        tgemm<<<dim3(32, 16), 256, TG_SMEM>>>(h, w1, b1, w1, b1,
                                              ff, M2, 4*HIDD, HIDD, 1 | 2, M2);
        const float* w2 = W2 + (size_t)l*4*HIDD*HIDD;
        const float* b2 = b2f + (size_t)l*HIDD;
        tgemm<<<dim3(8, 16), 256, TG_SMEM>>>(ff, w2, b2, w2, b2,
                                             tmp, M2, HIDD, 4*HIDD, 1, M2);
        addln_kernel<<<M2, 128>>>(h, tmp, ln2_g + (size_t)l*HIDD, ln2_b + (size_t)l*HIDD, x);
    }

    deinterleave<<<(M1*HIDD + 255)/256, 256>>>(x, fcb, fcb + M1*HIDD);
    sgemm64<<<dim3(2, 16), 256>>>(fcb,           out_lw, out_lb, out,           M1, HAND, HIDD, 1);
    sgemm64<<<dim3(2, 16), 256>>>(fcb + M1*HIDD, out_rw, out_rb, out + M1*HAND, M1, HAND, HIDD, 1);
}

// round 8
// speedup vs baseline: 1.9015x; 1.0341x over previous
#include <cuda_runtime.h>
#include <cuda_bf16.h>
#include <math.h>
#include <stdint.h>

// ---------------- problem constants ----------------
#define Bx      16
#define Lx      64
#define Nx      1024
#define HAND    99
#define Jx      21
#define HIDD    512
#define NLAYERS 4
#define NHEADS  8
#define DHD     64
#define CATD    2273
#define SEQ     128          // 2*Lx
#define M1      (Bx*Lx)      // 1024 rows per hand
#define M2      (Bx*SEQ)     // 2048 transformer rows

// ---------------- scratch (single __device__ arena) ----------------
#define OFF_PCT   0
#define SZ_PCT    (M1*Nx*3)
#define OFF_PCN   (OFF_PCT + SZ_PCT)
#define SZ_PCN    (M1*Nx)
#define OFF_ATT   (OFF_PCN + SZ_PCN)
#define SZ_ATT    (2*M1*Jx*3)
#define OFF_CAT   (OFF_ATT + SZ_ATT)
#define SZ_CAT    (2*M1*CATD)
#define OFF_FC    (OFF_CAT + SZ_CAT)
#define SZ_FC     (2 * 2*M1*HIDD)        // 2 K-split slices
#define OFF_X     (OFF_FC + SZ_FC)
#define SZ_X      (M2*HIDD)
#define OFF_H     (OFF_X + SZ_X)
#define SZ_H      (M2*HIDD)
#define OFF_QKV   (OFF_H + SZ_H)
#define SZ_QKV    (M2*3*HIDD)
#define OFF_AO    (OFF_QKV + SZ_QKV)
#define SZ_AO     (M2*HIDD)
#define OFF_FF    (OFF_AO + SZ_AO)
#define SZ_FF     (M2*4*HIDD)
#define OFF_TMP   (OFF_FF + SZ_FF)
#define SZ_TMP    (2 * M2*HIDD)          // 2 K-split slices
#define SCRATCH_TOTAL (OFF_TMP + SZ_TMP)

__device__ float g_scratch[SCRATCH_TOTAL];

// ---------------- rot6d + pc transform + norm ----------------
__global__ void transform_kernel(const float* __restrict__ x_obj,
                                 const float* __restrict__ pc,
                                 float* __restrict__ pct,
                                 float* __restrict__ pcn) {
    int bl = blockIdx.x;
    int b  = bl / Lx;
    const float* xo = x_obj + (size_t)bl * 10;
    float tx = xo[0], ty = xo[1], tz = xo[2];
    float a1x = xo[3], a1y = xo[4], a1z = xo[5];
    float a2x = xo[6], a2y = xo[7], a2z = xo[8];
    float n1 = sqrtf(a1x*a1x + a1y*a1y + a1z*a1z);
    float b1x = a1x/n1, b1y = a1y/n1, b1z = a1z/n1;
    float dd  = b1x*a2x + b1y*a2y + b1z*a2z;
    float b2x = a2x - dd*b1x, b2y = a2y - dd*b1y, b2z = a2z - dd*b1z;
    float n2 = sqrtf(b2x*b2x + b2y*b2y + b2z*b2z);
    b2x /= n2; b2y /= n2; b2z /= n2;
    float b3x = b1y*b2z - b1z*b2y;
    float b3y = b1z*b2x - b1x*b2z;
    float b3z = b1x*b2y - b1y*b2x;
    const float* pcb = pc + (size_t)b * Nx * 3;
    for (int n = threadIdx.x; n < Nx; n += blockDim.x) {
        float px = pcb[n*3+0], py = pcb[n*3+1], pz = pcb[n*3+2];
        float ox = b1x*px + b2x*py + b3x*pz + tx;
        float oy = b1y*px + b2y*py + b3y*pz + ty;
        float oz = b1z*px + b2z*py + b3z*pz + tz;
        float* o = pct + ((size_t)bl * Nx + n) * 3;
        o[0] = ox; o[1] = oy; o[2] = oz;
        pcn[(size_t)bl * Nx + n] = sqrtf(ox*ox + oy*oy + oz*oz);
    }
}

// ---------------- nearest-point attention map ----------------
__global__ void attmap_kernel(const float* __restrict__ jl,
                              const float* __restrict__ jr,
                              const float* __restrict__ pct,
                              float* __restrict__ att) {
    __shared__ float pcs[Nx*3];
    int bl = blockIdx.x, hand = blockIdx.y;
    const float* src = pct + (size_t)bl * Nx * 3;
    for (int i = threadIdx.x; i < Nx*3; i += blockDim.x) pcs[i] = src[i];
    __syncthreads();
    int w = threadIdx.x >> 5, lane = threadIdx.x & 31;
    if (w >= Jx) return;
    const float* jp = (hand ? jr : jl) + ((size_t)bl * Jx + w) * 3;
    float jx = jp[0], jy = jp[1], jz = jp[2];
    float jj = jx*jx + jy*jy + jz*jz;
    float best = 3.4e38f; int bidx = Nx;
    for (int n = lane; n < Nx; n += 32) {
        float px = pcs[n*3+0], py = pcs[n*3+1], pz = pcs[n*3+2];
        float pp = px*px + py*py + pz*pz;
        float d2 = jj + pp - 2.f*(jx*px + jy*py + jz*pz);
        if (d2 < best || (d2 == best && n < bidx)) { best = d2; bidx = n; }
    }
    for (int o = 16; o; o >>= 1) {
        float ob = __shfl_down_sync(0xffffffffu, best, o);
        int   oi = __shfl_down_sync(0xffffffffu, bidx, o);
        if (ob < best || (ob == best && oi < bidx)) { best = ob; bidx = oi; }
    }
    if (lane == 0) {
        float cx = pcs[bidx*3+0], cy = pcs[bidx*3+1], cz = pcs[bidx*3+2];
        float dx = jx - cx, dy = jy - cy, dz = jz - cz;
        float* o = att + ((size_t)hand * M1 * Jx + (size_t)bl * Jx + w) * 3;
        o[0] = expf(-50.f * dx*dx);
        o[1] = expf(-50.f * dy*dy);
        o[2] = expf(-50.f * dz*dz);
    }
}

// ---------------- concat feature assembly ----------------
__global__ void buildcat_kernel(const float* __restrict__ xl, const float* __restrict__ xr,
                                const float* __restrict__ jl, const float* __restrict__ jr,
                                const float* __restrict__ mc, const float* __restrict__ pcn,
                                const float* __restrict__ att, float* __restrict__ cat) {
    int bl = blockIdx.x, hand = blockIdx.y;
    int b = bl / Lx;
    float* dst = cat + ((size_t)hand * M1 + bl) * CATD;
    const float* xh = hand ? xr : xl;
    const float* jh = hand ? jr : jl;
    for (int c = threadIdx.x; c < CATD; c += blockDim.x) {
        float v;
        if (c < 99)        v = xh[(size_t)bl * HAND + c];
        else if (c < 162)  v = jh[(size_t)bl * 63 + (c - 99)];
        else if (c < 1186) v = mc[(size_t)b * Nx + (c - 162)];
        else if (c < 2210) v = pcn[(size_t)bl * Nx + (c - 1186)];
        else               v = att[(size_t)hand * M1 * 63 + (size_t)bl * 63 + (c - 2210)];
        dst[c] = v;
    }
}

// ---------------- bf16 helpers ----------------
__device__ __forceinline__ uint32_t pack_bf16(float e, float o) {
    uint32_t r;
    asm("cvt.rn.bf16x2.f32 %0, %1, %2;" : "=r"(r) : "f"(o), "f"(e));
    return r;
}
__device__ __forceinline__ float2 unpack_bf16(uint32_t w) {
    float2 f;
    f.x = __uint_as_float(w << 16);
    f.y = __uint_as_float(w & 0xffff0000u);
    return f;
}
__device__ __forceinline__ void split_pair(float e, float o, uint32_t& hw, uint32_t& lw) {
    hw = pack_bf16(e, o);
    float2 hf = unpack_bf16(hw);
    lw = pack_bf16(e - hf.x, o - hf.y);
}
__device__ __forceinline__ void mma_bf16(float* c, const uint32_t* a, const uint32_t* b) {
    asm("mma.sync.aligned.m16n8k16.row.col.f32.bf16.bf16.f32 "
        "{%0,%1,%2,%3}, {%4,%5,%6,%7}, {%8,%9}, {%0,%1,%2,%3};\n"
        : "+f"(c[0]), "+f"(c[1]), "+f"(c[2]), "+f"(c[3])
        : "r"(a[0]), "r"(a[1]), "r"(a[2]), "r"(a[3]), "r"(b[0]), "r"(b[1]));
}

// ---------------- bf16x3 tensor-core GEMM (m16n8k16), double-buffered, K-split ----------------
// Block tile 128x64x32, 8 warps (4m x 2n), warp tile 32x32.
// blockIdx.z = K-split slice; each slice writes C + z*cstride. Bias only on z==0.
#define TBM 128
#define TBN 64
#define TBK 32
#define AST 20
#define BST 72
#define TASZ (TBM*AST)        // 2560 words per copy
#define TBSZ (16*BST)         // 1152 words per copy
#define TG_SMEM ((4*TASZ + 4*TBSZ) * 4)  // 2 stages * (hi+lo) = 59392 B

__global__ void __launch_bounds__(256, 2)
tgemm(const float* __restrict__ A,
      const float* __restrict__ B1, const float* __restrict__ bias1,
      const float* __restrict__ B2, const float* __restrict__ bias2,
      float* __restrict__ C, int M, int N, int K, int flags, int rowsplit,
      int ksplit, size_t cstride) {
    extern __shared__ uint32_t smw[];
    uint32_t* Ah = smw;                    // [2][TASZ]
    uint32_t* Al = Ah + 2*TASZ;
    uint32_t* Bh = Al + 2*TASZ;            // [2][TBSZ]
    uint32_t* Bl = Bh + 2*TBSZ;

    int tid = threadIdx.x;
    int row0 = blockIdx.y * TBM, col0 = blockIdx.x * TBN;
    const float* Bw   = (row0 >= rowsplit) ? B2 : B1;
    const float* bias = (row0 >= rowsplit) ? bias2 : bias1;

    // K-split range
    int Klen = (((K + ksplit - 1) / ksplit) + TBK - 1) / TBK * TBK;
    int kbeg = blockIdx.z * Klen;
    int kend = min(K, kbeg + Klen);
    C += (size_t)blockIdx.z * cstride;
    bool dobias = (flags & 1) && (blockIdx.z == 0);

    int warp = tid >> 5, lane = tid & 31;
    int wm = warp & 3, wn = warp >> 2;
    int m0 = wm * 32, n0 = wn * 32;
    int g = lane >> 2, t = lane & 3;

    float acc[2][4][4];
    #pragma unroll
    for (int mi = 0; mi < 2; mi++)
        #pragma unroll
        for (int ni = 0; ni < 4; ni++)
            #pragma unroll
            for (int j = 0; j < 4; j++) acc[mi][ni][j] = 0.f;

    const bool vecA = ((K & 3) == 0);
    const int ntiles = (kend - kbeg + TBK - 1) / TBK;

    float4 pa[4];
    float  pas[16];
    float4 pb0, pb1;

    const int a_m  = tid >> 3,  a_k4 = (tid & 7) * 4;
    const int b_kp = tid >> 4,  b_nq = tid & 15;

    auto load_tile = [&](int ti) {
        int k0 = kbeg + ti * TBK;
        if (vecA) {
            #pragma unroll
            for (int i = 0; i < 4; i++) {
                int m = a_m + i*32;
                int gk = k0 + a_k4;
                if (gk < kend) pa[i] = *(const float4*)(A + (size_t)(row0 + m)*K + gk);
                else           pa[i] = make_float4(0.f,0.f,0.f,0.f);
            }
        } else {
            #pragma unroll
            for (int i = 0; i < 8; i++) {
                int idx = tid + i*256;
                int m = idx >> 4, kw = idx & 15;
                int gk = k0 + kw*2;
                pas[2*i]   = (gk     < kend) ? A[(size_t)(row0 + m)*K + gk]     : 0.f;
                pas[2*i+1] = (gk + 1 < kend) ? A[(size_t)(row0 + m)*K + gk + 1] : 0.f;
            }
        }
        int gk0 = k0 + 2*b_kp, gk1 = gk0 + 1;
        if (gk0 < kend) pb0 = *(const float4*)(Bw + (size_t)gk0*N + col0 + b_nq*4);
        else            pb0 = make_float4(0.f,0.f,0.f,0.f);
        if (gk1 < kend) pb1 = *(const float4*)(Bw + (size_t)gk1*N + col0 + b_nq*4);
        else            pb1 = make_float4(0.f,0.f,0.f,0.f);
    };

    auto store_tile = [&](int st) {
        uint32_t* AhS = Ah + st*TASZ; uint32_t* AlS = Al + st*TASZ;
        uint32_t* BhS = Bh + st*TBSZ; uint32_t* BlS = Bl + st*TBSZ;
        if (vecA) {
            #pragma unroll
            for (int i = 0; i < 4; i++) {
                int m = a_m + i*32;
                int kw0 = a_k4 >> 1;
                uint32_t h0,l0,h1,l1;
                split_pair(pa[i].x, pa[i].y, h0, l0);
                split_pair(pa[i].z, pa[i].w, h1, l1);
                *(uint2*)(AhS + m*AST + kw0) = make_uint2(h0, h1);
                *(uint2*)(AlS + m*AST + kw0) = make_uint2(l0, l1);
            }
        } else {
            #pragma unroll
            for (int i = 0; i < 8; i++) {
                int idx = tid + i*256;
                int m = idx >> 4, kw = idx & 15;
                uint32_t hw, lw;
                split_pair(pas[2*i], pas[2*i+1], hw, lw);
                AhS[m*AST + kw] = hw;
                AlS[m*AST + kw] = lw;
            }
        }
        {
            uint32_t hw[4], lw[4];
            split_pair(pb0.x, pb1.x, hw[0], lw[0]);
            split_pair(pb0.y, pb1.y, hw[1], lw[1]);
            split_pair(pb0.z, pb1.z, hw[2], lw[2]);
            split_pair(pb0.w, pb1.w, hw[3], lw[3]);
            *(uint4*)(BhS + b_kp*BST + b_nq*4) = make_uint4(hw[0],hw[1],hw[2],hw[3]);
            *(uint4*)(BlS + b_kp*BST + b_nq*4) = make_uint4(lw[0],lw[1],lw[2],lw[3]);
        }
    };

    load_tile(0);
    store_tile(0);
    __syncthreads();

    for (int ti = 0; ti < ntiles; ti++) {
        int st = ti & 1;
        if (ti + 1 < ntiles) load_tile(ti + 1);

        const uint32_t* AhS = Ah + st*TASZ; const uint32_t* AlS = Al + st*TASZ;
        const uint32_t* BhS = Bh + st*TBSZ; const uint32_t* BlS = Bl + st*TBSZ;
        #pragma unroll
        for (int ks = 0; ks < 2; ks++) {
            int kw = ks*8 + t;
            uint32_t ahr[2][4], alr[2][4];
            #pragma unroll
            for (int mi = 0; mi < 2; mi++) {
                int mr = m0 + mi*16 + g;
                ahr[mi][0] = AhS[mr*AST + kw];
                ahr[mi][1] = AhS[(mr+8)*AST + kw];
                ahr[mi][2] = AhS[mr*AST + kw + 4];
                ahr[mi][3] = AhS[(mr+8)*AST + kw + 4];
                alr[mi][0] = AlS[mr*AST + kw];
                alr[mi][1] = AlS[(mr+8)*AST + kw];
                alr[mi][2] = AlS[mr*AST + kw + 4];
                alr[mi][3] = AlS[(mr+8)*AST + kw + 4];
            }
            #pragma unroll
            for (int ni = 0; ni < 4; ni++) {
                int n = n0 + ni*8 + g;
                uint32_t bhr[2], blr[2];
                bhr[0] = BhS[kw*BST + n];
                bhr[1] = BhS[(kw+4)*BST + n];
                blr[0] = BlS[kw*BST + n];
                blr[1] = BlS[(kw+4)*BST + n];
                #pragma unroll
                for (int mi = 0; mi < 2; mi++) {
                    mma_bf16(acc[mi][ni], ahr[mi], bhr);
                    mma_bf16(acc[mi][ni], alr[mi], bhr);
                    mma_bf16(acc[mi][ni], ahr[mi], blr);
                }
            }
        }
        if (ti + 1 < ntiles) store_tile((ti + 1) & 1);
        __syncthreads();
    }

    // ---- epilogue ----
    #pragma unroll
    for (int mi = 0; mi < 2; mi++) {
        int r = row0 + m0 + mi*16 + g;
        #pragma unroll
        for (int ni = 0; ni < 4; ni++) {
            int c = col0 + n0 + ni*8 + 2*t;
            float v0 = acc[mi][ni][0], v1 = acc[mi][ni][1];
            float v2 = acc[mi][ni][2], v3 = acc[mi][ni][3];
            if (dobias) {
                float b0v = bias[c], b1v = bias[c+1];
                v0 += b0v; v1 += b1v; v2 += b0v; v3 += b1v;
            }
            if (flags & 2) {
                v0 = fmaxf(v0, 0.f); v1 = fmaxf(v1, 0.f);
                v2 = fmaxf(v2, 0.f); v3 = fmaxf(v3, 0.f);
            }
            C[(size_t)r*N + c]       = v0;
            C[(size_t)r*N + c + 1]   = v1;
            C[(size_t)(r+8)*N + c]   = v2;
            C[(size_t)(r+8)*N + c+1] = v3;
        }
    }
}

// ---------------- SGEMM 64x64x16 (small output heads only) ----------------
__global__ void sgemm64(const float* __restrict__ A, const float* __restrict__ Bw,
                        const float* __restrict__ bias, float* __restrict__ C,
                        int M, int N, int K, int flags) {
    __shared__ float As[16][65];
    __shared__ float Bs[16][65];
    int tid = threadIdx.x, tx = tid & 15, ty = tid >> 4;
    int row0 = blockIdx.y * 64, col0 = blockIdx.x * 64;
    float acc[4][4] = {};
    for (int k0 = 0; k0 < K; k0 += 16) {
        #pragma unroll
        for (int i = 0; i < 4; i++) {
            int idx = tid + i*256; int m = idx >> 4, kk = idx & 15;
            int gr = row0 + m, gk = k0 + kk;
            As[kk][m] = (gr < M && gk < K) ? A[(size_t)gr*K + gk] : 0.f;
        }
        #pragma unroll
        for (int i = 0; i < 4; i++) {
            int idx = tid + i*256; int kk = idx >> 6, n = idx & 63;
            int gk = k0 + kk, gc = col0 + n;
            Bs[kk][n] = (gk < K && gc < N) ? Bw[(size_t)gk*N + gc] : 0.f;
        }
        __syncthreads();
        #pragma unroll
        for (int kk = 0; kk < 16; kk++) {
            float a[4], b[4];
            #pragma unroll
            for (int i = 0; i < 4; i++) a[i] = As[kk][ty*4+i];
            #pragma unroll
            for (int j = 0; j < 4; j++) b[j] = Bs[kk][tx*4+j];
            #pragma unroll
            for (int i = 0; i < 4; i++)
                #pragma unroll
                for (int j = 0; j < 4; j++) acc[i][j] += a[i]*b[j];
        }
        __syncthreads();
    }
    #pragma unroll
    for (int i = 0; i < 4; i++) {
        int r = row0 + ty*4 + i; if (r >= M) continue;
        #pragma unroll
        for (int j = 0; j < 4; j++) {
            int c = col0 + tx*4 + j; if (c >= N) continue;
            float v = acc[i][j];
            if (flags & 1) v += bias[c];
            if (flags & 2) v = fmaxf(v, 0.f);
            C[(size_t)r*N + c] = v;
        }
    }
}

// ---------------- interleave L/R (two K-split slices) + positional encodings ----------------
__global__ void interleave_pe(const float* __restrict__ fl, const float* __restrict__ fr,
                              int poff, float* __restrict__ x) {
    int idx = blockIdx.x * blockDim.x + threadIdx.x;
    if (idx >= M2*HIDD) return;
    int d = idx & (HIDD - 1);
    int srow = idx >> 9;
    int s = srow & (SEQ - 1);
    int b = srow >> 7;
    int l = s >> 1, h = s & 1;
    const float* src = h ? fr : fl;
    size_t base = ((size_t)(b*Lx + l)) * HIDD + d;
    float v = src[base] + src[base + poff];
    int i2 = d & ~1;
    float div = expf((float)i2 * (-9.2103403719761836f / 512.f));
    float pl = (d & 1) ? cosf((float)l * div) : sinf((float)l * div);
    float pa = (d & 1) ? cosf((float)h * div) : sinf((float)h * div);
    x[idx] = v + pl + pa;
}

// ---------------- per-(b,h) attention ----------------
#define ATTN_SMEM ((2*SEQ*DHD + SEQ*129) * 4)
__global__ void attn_kernel(const float* __restrict__ qkv, float* __restrict__ out) {
    extern __shared__ float sm[];
    float* Ks = sm;
    float* Vs = sm + SEQ*DHD;
    float* Ss = sm + 2*SEQ*DHD;
    int b = blockIdx.x >> 3, h = blockIdx.x & 7;
    int i = threadIdx.x;
    for (int idx = i; idx < SEQ*DHD; idx += blockDim.x) {
        int s = idx >> 6, d = idx & 63;
        size_t base = ((size_t)(b*SEQ + s)) * 1536 + h*64 + d;
        Ks[idx] = qkv[base + 512];
        Vs[idx] = qkv[base + 1024];
    }
    float q[DHD];
    {
        size_t base = ((size_t)(b*SEQ + i)) * 1536 + h*64;
        #pragma unroll
        for (int d = 0; d < DHD; d++) q[d] = qkv[base + d];
    }
    __syncthreads();
    float m = -3.4e38f;
    float* srow = Ss + i*129;
    for (int k = 0; k < SEQ; k++) {
        float s = 0.f;
        #pragma unroll
        for (int d = 0; d < DHD; d++) s += q[d] * Ks[k*64 + d];
        s *= 0.125f;
        srow[k] = s;
        m = fmaxf(m, s);
    }
    float sum = 0.f;
    for (int k = 0; k < SEQ; k++) {
        float e = expf(srow[k] - m);
        srow[k] = e; sum += e;
    }
    float inv = 1.f / sum;
    size_t obase = ((size_t)(b*SEQ + i)) * HIDD + h*64;
    for (int d0 = 0; d0 < DHD; d0 += 16) {
        float acc[16] = {};
        for (int k = 0; k < SEQ; k++) {
            float p = srow[k];
            #pragma unroll
            for (int dd = 0; dd < 16; dd++) acc[dd] += p * Vs[k*64 + d0 + dd];
        }
        #pragma unroll
        for (int dd = 0; dd < 16; dd++) out[obase + d0 + dd] = acc[dd] * inv;
    }
}

// ---------------- residual + two-slice partial + layernorm ----------------
__global__ void addln_kernel(const float* __restrict__ a, const float* __restrict__ r,
                             const float* __restrict__ r2,
                             const float* __restrict__ g, const float* __restrict__ be,
                             float* __restrict__ out) {
    int row = blockIdx.x;
    int t = threadIdx.x;
    const float* pa  = a  + (size_t)row * HIDD;
    const float* pr  = r  + (size_t)row * HIDD;
    const float* pr2 = r2 + (size_t)row * HIDD;
    float v[4];
    #pragma unroll
    for (int i = 0; i < 4; i++) { int c = t + i*128; v[i] = pa[c] + pr[c] + pr2[c]; }
    float s = v[0] + v[1] + v[2] + v[3];
    __shared__ float sh[4];
    for (int o = 16; o; o >>= 1) s += __shfl_down_sync(0xffffffffu, s, o);
    int lane = t & 31, w = t >> 5;
    if (lane == 0) sh[w] = s;
    __syncthreads();
    float mu = (sh[0] + sh[1] + sh[2] + sh[3]) * (1.f / HIDD);
    float qv = 0.f;
    #pragma unroll
    for (int i = 0; i < 4; i++) { float d = v[i] - mu; qv += d*d; }
    __syncthreads();
    for (int o = 16; o; o >>= 1) qv += __shfl_down_sync(0xffffffffu, qv, o);
    if (lane == 0) sh[w] = qv;
    __syncthreads();
    float var = (sh[0] + sh[1] + sh[2] + sh[3]) * (1.f / HIDD);
    float inv = rsqrtf(var + 1e-5f);
    float* po = out + (size_t)row * HIDD;
    #pragma unroll
    for (int i = 0; i < 4; i++) { int c = t + i*128; po[c] = (v[i] - mu)*inv*g[c] + be[c]; }
}

// ---------------- deinterleave even/odd rows ----------------
__global__ void deinterleave(const float* __restrict__ x,
                             float* __restrict__ fl, float* __restrict__ fr) {
    int idx = blockIdx.x * blockDim.x + threadIdx.x;
    if (idx >= M1*HIDD) return;
    int d = idx & 511; int bl = idx >> 9;
    int b = bl >> 6, l = bl & 63;
    fl[idx] = x[((size_t)(b*SEQ + 2*l    )) * HIDD + d];
    fr[idx] = x[((size_t)(b*SEQ + 2*l + 1)) * HIDD + d];
}

// ---------------- launch ----------------
extern "C" void kernel_launch(void* const* d_in, const int* in_sizes, int n_in,
                              void* d_out, int out_size) {
    const float* x_lhand     = (const float*)d_in[0];
    const float* x_rhand     = (const float*)d_in[1];
    const float* j_lhand     = (const float*)d_in[2];
    const float* j_rhand     = (const float*)d_in[3];
    const float* m_contact   = (const float*)d_in[4];
    const float* x_obj       = (const float*)d_in[5];
    const float* point_cloud = (const float*)d_in[6];
    const float* fc_lw  = (const float*)d_in[7];
    const float* fc_lb  = (const float*)d_in[8];
    const float* fc_rw  = (const float*)d_in[9];
    const float* fc_rb  = (const float*)d_in[10];
    const float* out_lw = (const float*)d_in[11];
    const float* out_lb = (const float*)d_in[12];
    const float* out_rw = (const float*)d_in[13];
    const float* out_rb = (const float*)d_in[14];
    const float* Wqkv   = (const float*)d_in[15];
    const float* bqkv   = (const float*)d_in[16];
    const float* Wo     = (const float*)d_in[17];
    const float* bo     = (const float*)d_in[18];
    const float* W1     = (const float*)d_in[19];
    const float* b1f    = (const float*)d_in[20];
    const float* W2     = (const float*)d_in[21];
    const float* b2f    = (const float*)d_in[22];
    const float* ln1_g  = (const float*)d_in[23];
    const float* ln1_b  = (const float*)d_in[24];
    const float* ln2_g  = (const float*)d_in[25];
    const float* ln2_b  = (const float*)d_in[26];
    float* out = (float*)d_out;

    float* base = nullptr;
    cudaGetSymbolAddress((void**)&base, g_scratch);
    float* pct = base + OFF_PCT;
    float* pcn = base + OFF_PCN;
    float* att = base + OFF_ATT;
    float* cat = base + OFF_CAT;
    float* fcb = base + OFF_FC;
    float* x   = base + OFF_X;
    float* h   = base + OFF_H;
    float* qkv = base + OFF_QKV;
    float* ao  = base + OFF_AO;
    float* ff  = base + OFF_FF;
    float* tmp = base + OFF_TMP;

    cudaFuncSetAttribute(attn_kernel, cudaFuncAttributeMaxDynamicSharedMemorySize, ATTN_SMEM);
    cudaFuncSetAttribute(tgemm, cudaFuncAttributeMaxDynamicSharedMemorySize, TG_SMEM);

    const size_t FCST  = (size_t)2*M1*HIDD;   // fc slice stride
    const size_t TMPST = (size_t)M2*HIDD;     // tmp slice stride

    transform_kernel<<<M1, 256>>>(x_obj, point_cloud, pct, pcn);
    attmap_kernel<<<dim3(M1, 2), Jx*32>>>(j_lhand, j_rhand, pct, att);
    buildcat_kernel<<<dim3(M1, 2), 256>>>(x_lhand, x_rhand, j_lhand, j_rhand,
                                          m_contact, pcn, att, cat);

    // fused both-hand input projection, K-split 2: [2048 x 2273] @ [2273 x 512]
    tgemm<<<dim3(8, 16, 2), 256, TG_SMEM>>>(cat, fc_lw, fc_lb, fc_rw, fc_rb,
                                            fcb, 2*M1, HIDD, CATD, 1, M1, 2, FCST);
    interleave_pe<<<(M2*HIDD + 255)/256, 256>>>(fcb, fcb + M1*HIDD, (int)FCST, x);

    for (int l = 0; l < NLAYERS; l++) {
        const float* wq = Wqkv + (size_t)l*HIDD*3*HIDD;
        const float* bq = bqkv + (size_t)l*3*HIDD;
        tgemm<<<dim3(24, 16, 1), 256, TG_SMEM>>>(x, wq, bq, wq, bq,
                                                 qkv, M2, 3*HIDD, HIDD, 1, M2, 1, 0);
        attn_kernel<<<Bx*NHEADS, SEQ, ATTN_SMEM>>>(qkv, ao);
        const float* wo = Wo + (size_t)l*HIDD*HIDD;
        const float* bob = bo + (size_t)l*HIDD;
        tgemm<<<dim3(8, 16, 2), 256, TG_SMEM>>>(ao, wo, bob, wo, bob,
                                                tmp, M2, HIDD, HIDD, 1, M2, 2, TMPST);
        addln_kernel<<<M2, 128>>>(x, tmp, tmp + TMPST,
                                  ln1_g + (size_t)l*HIDD, ln1_b + (size_t)l*HIDD, h);
        const float* w1 = W1 + (size_t)l*HIDD*4*HIDD;
        const float* b1 = b1f + (size_t)l*4*HIDD;
        tgemm<<<dim3(32, 16, 1), 256, TG_SMEM>>>(h, w1, b1, w1, b1,
                                                 ff, M2, 4*HIDD, HIDD, 1 | 2, M2, 1, 0);
        const float* w2 = W2 + (size_t)l*4*HIDD*HIDD;
        const float* b2 = b2f + (size_t)l*HIDD;
        tgemm<<<dim3(8, 16, 2), 256, TG_SMEM>>>(ff, w2, b2, w2, b2,
                                                tmp, M2, HIDD, 4*HIDD, 1, M2, 2, TMPST);
        addln_kernel<<<M2, 128>>>(h, tmp, tmp + TMPST,
                                  ln2_g + (size_t)l*HIDD, ln2_b + (size_t)l*HIDD, x);
    }

    deinterleave<<<(M1*HIDD + 255)/256, 256>>>(x, fcb, fcb + M1*HIDD);
    sgemm64<<<dim3(2, 16), 256>>>(fcb,           out_lw, out_lb, out,           M1, HAND, HIDD, 1);
    sgemm64<<<dim3(2, 16), 256>>>(fcb + M1*HIDD, out_rw, out_rb, out + M1*HAND, M1, HAND, HIDD, 1);
}